// round 3
// baseline (speedup 1.0000x reference)
#include <cuda_runtime.h>

#define D_MODEL 1024
#define NHEADS  16
#define HDIM    64
#define BATCH   2
#define SEQ     2048
#define NROWS   (BATCH * SEQ)   // 4096

// ---------------- scratch (static device globals; no allocations) ----------------
__device__ float g_Q[BATCH * NHEADS * SEQ * HDIM];    // [B,H,S,Dh] 16 MB
__device__ float g_K[BATCH * NHEADS * SEQ * HDIM];
__device__ float g_V[BATCH * NHEADS * SEQ * HDIM];
__device__ float g_Ctx[NROWS * D_MODEL];              // [B*S, D] attention output

// =================================================================================
// QKV GEMM: for z in {0,1,2}: P_z = x[4096x1024] @ W_z[1024x1024], scattered to
// [B,H,S,Dh] layout in g_Q/g_K/g_V. 128x128 block tile, BK=16, 256 threads,
// 8x8 register micro-tile. grid = (8, 32, 3). Static smem only.
// =================================================================================
__global__ __launch_bounds__(256) void qkv_gemm_kernel(
    const float* __restrict__ A,
    const float* __restrict__ Wq, const float* __restrict__ Wk,
    const float* __restrict__ Wv)
{
    constexpr int BK    = 16;
    constexpr int PITCH = 132;                 // 128 + 4 pad
    __shared__ float Xs[BK * PITCH];           // transposed: Xs[k][m]
    __shared__ float Ws[BK * PITCH];           // natural:    Ws[k][n]

    const float* W = (blockIdx.z == 0) ? Wq : (blockIdx.z == 1) ? Wk : Wv;
    float* C       = (blockIdx.z == 0) ? g_Q : (blockIdx.z == 1) ? g_K : g_V;

    const int t  = threadIdx.x;
    const int tx = t & 15;
    const int ty = t >> 4;
    const int m0 = blockIdx.y * 128;
    const int n0 = blockIdx.x * 128;

    float acc[8][8];
#pragma unroll
    for (int i = 0; i < 8; i++)
#pragma unroll
        for (int j = 0; j < 8; j++) acc[i][j] = 0.0f;

    for (int k0 = 0; k0 < D_MODEL; k0 += BK) {
#pragma unroll
        for (int i = 0; i < 2; i++) {
            int idx = t + i * 256;
            int row = idx >> 2;
            int c4  = (idx & 3) * 4;
            float4 v = *(const float4*)(A + (size_t)(m0 + row) * D_MODEL + k0 + c4);
            Xs[(c4 + 0) * PITCH + row] = v.x;
            Xs[(c4 + 1) * PITCH + row] = v.y;
            Xs[(c4 + 2) * PITCH + row] = v.z;
            Xs[(c4 + 3) * PITCH + row] = v.w;
        }
#pragma unroll
        for (int i = 0; i < 2; i++) {
            int idx = t + i * 256;
            int row = idx >> 5;
            int c4  = (idx & 31) * 4;
            *(float4*)(Ws + row * PITCH + c4) =
                *(const float4*)(W + (size_t)(k0 + row) * D_MODEL + n0 + c4);
        }
        __syncthreads();

#pragma unroll
        for (int kk = 0; kk < BK; kk++) {
            float a[8], bv[8];
            *(float4*)&a[0]  = *(const float4*)(Xs + kk * PITCH + ty * 8);
            *(float4*)&a[4]  = *(const float4*)(Xs + kk * PITCH + ty * 8 + 4);
            *(float4*)&bv[0] = *(const float4*)(Ws + kk * PITCH + tx * 8);
            *(float4*)&bv[4] = *(const float4*)(Ws + kk * PITCH + tx * 8 + 4);
#pragma unroll
            for (int i = 0; i < 8; i++)
#pragma unroll
                for (int j = 0; j < 8; j++)
                    acc[i][j] = fmaf(a[i], bv[j], acc[i][j]);
        }
        __syncthreads();
    }

#pragma unroll
    for (int i = 0; i < 8; i++) {
        const int m = m0 + ty * 8 + i;
        const int b = m >> 11;               // m / SEQ
        const int s = m & (SEQ - 1);
#pragma unroll
        for (int j = 0; j < 8; j++) {
            const int n  = n0 + tx * 8 + j;
            const int h  = n >> 6;           // n / HDIM
            const int dd = n & (HDIM - 1);
            C[(((size_t)(b * NHEADS + h)) * SEQ + s) * HDIM + dd] = acc[i][j];
        }
    }
}

// =================================================================================
// Output GEMM: out = g_Ctx[4096x1024] @ Wo[1024x1024], plain row-major output.
// =================================================================================
__global__ __launch_bounds__(256) void out_gemm_kernel(
    const float* __restrict__ W, float* __restrict__ C)
{
    constexpr int BK    = 16;
    constexpr int PITCH = 132;
    __shared__ float Xs[BK * PITCH];
    __shared__ float Ws[BK * PITCH];
    const float* A = g_Ctx;

    const int t  = threadIdx.x;
    const int tx = t & 15;
    const int ty = t >> 4;
    const int m0 = blockIdx.y * 128;
    const int n0 = blockIdx.x * 128;

    float acc[8][8];
#pragma unroll
    for (int i = 0; i < 8; i++)
#pragma unroll
        for (int j = 0; j < 8; j++) acc[i][j] = 0.0f;

    for (int k0 = 0; k0 < D_MODEL; k0 += BK) {
#pragma unroll
        for (int i = 0; i < 2; i++) {
            int idx = t + i * 256;
            int row = idx >> 2;
            int c4  = (idx & 3) * 4;
            float4 v = *(const float4*)(A + (size_t)(m0 + row) * D_MODEL + k0 + c4);
            Xs[(c4 + 0) * PITCH + row] = v.x;
            Xs[(c4 + 1) * PITCH + row] = v.y;
            Xs[(c4 + 2) * PITCH + row] = v.z;
            Xs[(c4 + 3) * PITCH + row] = v.w;
        }
#pragma unroll
        for (int i = 0; i < 2; i++) {
            int idx = t + i * 256;
            int row = idx >> 5;
            int c4  = (idx & 31) * 4;
            *(float4*)(Ws + row * PITCH + c4) =
                *(const float4*)(W + (size_t)(k0 + row) * D_MODEL + n0 + c4);
        }
        __syncthreads();

#pragma unroll
        for (int kk = 0; kk < BK; kk++) {
            float a[8], bv[8];
            *(float4*)&a[0]  = *(const float4*)(Xs + kk * PITCH + ty * 8);
            *(float4*)&a[4]  = *(const float4*)(Xs + kk * PITCH + ty * 8 + 4);
            *(float4*)&bv[0] = *(const float4*)(Ws + kk * PITCH + tx * 8);
            *(float4*)&bv[4] = *(const float4*)(Ws + kk * PITCH + tx * 8 + 4);
#pragma unroll
            for (int i = 0; i < 8; i++)
#pragma unroll
                for (int j = 0; j < 8; j++)
                    acc[i][j] = fmaf(a[i], bv[j], acc[i][j]);
        }
        __syncthreads();
    }

#pragma unroll
    for (int i = 0; i < 8; i++) {
        const int m = m0 + ty * 8 + i;
#pragma unroll
        for (int j = 0; j < 8; j++)
            C[(size_t)m * D_MODEL + (n0 + tx * 8 + j)] = acc[i][j];
    }
}

// =================================================================================
// Causal flash attention, fp32. One block = 64 queries of one (b,h).
// 256 threads as 16x16; 4x4 micro-tiles. Online softmax via 16-lane shuffles.
// STATIC shared memory only (48 KB exactly): Qs, Vs, and Ks aliased with Ps
// (probs overwrite the K tile after S=QK^T is computed).
// =================================================================================
__global__ __launch_bounds__(256) void attn_kernel()
{
    constexpr int P = 64;                       // pitch (no pad; 3*64*64*4 = 49152 B)
    __shared__ float Qs[64 * P];                // [d][q]  (transposed)
    __shared__ float KPs[64 * P];               // [d][c] as K, then [c][r] as probs
    __shared__ float Vs[64 * P];                // [c][d]  (natural)

    const int t  = threadIdx.x;
    const int tx = t & 15;
    const int ty = t >> 4;
    const int qt = blockIdx.x;       // query tile (0..31)
    const int h  = blockIdx.y;
    const int b  = blockIdx.z;
    const int bh = b * NHEADS + h;
    const float* Qb = g_Q + (size_t)bh * SEQ * HDIM;
    const float* Kb = g_K + (size_t)bh * SEQ * HDIM;
    const float* Vb = g_V + (size_t)bh * SEQ * HDIM;
    const int q0 = qt * 64;

    // load Q tile (64 x 64) transposed into Qs
#pragma unroll
    for (int i = 0; i < 4; i++) {
        int idx = t + i * 256;
        int r   = idx >> 4;
        int c4  = (idx & 15) * 4;
        float4 v = *(const float4*)(Qb + (size_t)(q0 + r) * HDIM + c4);
        Qs[(c4 + 0) * P + r] = v.x;
        Qs[(c4 + 1) * P + r] = v.y;
        Qs[(c4 + 2) * P + r] = v.z;
        Qs[(c4 + 3) * P + r] = v.w;
    }

    float m_[4], l_[4], o_[4][4];
#pragma unroll
    for (int i = 0; i < 4; i++) {
        m_[i] = -1e30f;
        l_[i] = 0.0f;
#pragma unroll
        for (int j = 0; j < 4; j++) o_[i][j] = 0.0f;
    }

    for (int jt = 0; jt <= qt; jt++) {
        __syncthreads();   // previous iteration done reading KPs(probs)/Vs
        const float* Kt = Kb + (size_t)jt * 64 * HDIM;
        const float* Vt = Vb + (size_t)jt * 64 * HDIM;
#pragma unroll
        for (int i = 0; i < 4; i++) {
            int idx = t + i * 256;
            int r   = idx >> 4;
            int c4  = (idx & 15) * 4;
            float4 kv = *(const float4*)(Kt + (size_t)r * HDIM + c4);
            KPs[(c4 + 0) * P + r] = kv.x;
            KPs[(c4 + 1) * P + r] = kv.y;
            KPs[(c4 + 2) * P + r] = kv.z;
            KPs[(c4 + 3) * P + r] = kv.w;
            *(float4*)(Vs + r * P + c4) = *(const float4*)(Vt + (size_t)r * HDIM + c4);
        }
        __syncthreads();

        // S = Q @ K^T  (4x4 per thread)
        float s_[4][4];
#pragma unroll
        for (int i = 0; i < 4; i++)
#pragma unroll
            for (int j = 0; j < 4; j++) s_[i][j] = 0.0f;
#pragma unroll
        for (int kk = 0; kk < 64; kk++) {
            float a[4], bv[4];
            *(float4*)a  = *(const float4*)(Qs + kk * P + ty * 4);
            *(float4*)bv = *(const float4*)(KPs + kk * P + tx * 4);
#pragma unroll
            for (int i = 0; i < 4; i++)
#pragma unroll
                for (int j = 0; j < 4; j++)
                    s_[i][j] = fmaf(a[i], bv[j], s_[i][j]);
        }
        __syncthreads();   // everyone finished reading K before probs overwrite it

        // scale + causal mask (only diagonal tile can mask)
        const bool diag = (jt == qt);
#pragma unroll
        for (int i = 0; i < 4; i++) {
            const int qg = q0 + ty * 4 + i;
#pragma unroll
            for (int j = 0; j < 4; j++) {
                float v = s_[i][j] * 0.125f;       // 1/sqrt(64)
                const int kg = jt * 64 + tx * 4 + j;
                if (diag && kg > qg) v = -1e30f;
                s_[i][j] = v;
            }
        }

        // online softmax per row (reduce over the 16 tx lanes in this row group)
#pragma unroll
        for (int i = 0; i < 4; i++) {
            float tm = fmaxf(fmaxf(s_[i][0], s_[i][1]), fmaxf(s_[i][2], s_[i][3]));
#pragma unroll
            for (int off = 8; off > 0; off >>= 1)
                tm = fmaxf(tm, __shfl_xor_sync(0xffffffffu, tm, off));
            const float nm    = fmaxf(m_[i], tm);
            const float alpha = __expf(m_[i] - nm);
            float rs = 0.0f;
#pragma unroll
            for (int j = 0; j < 4; j++) {
                float p = __expf(s_[i][j] - nm);
                s_[i][j] = p;
                rs += p;
            }
#pragma unroll
            for (int off = 8; off > 0; off >>= 1)
                rs += __shfl_xor_sync(0xffffffffu, rs, off);
            l_[i] = l_[i] * alpha + rs;
            m_[i] = nm;
#pragma unroll
            for (int j = 0; j < 4; j++) o_[i][j] *= alpha;
        }

        // P -> smem (transposed: KPs[c][r]), reusing the K buffer
#pragma unroll
        for (int i = 0; i < 4; i++)
#pragma unroll
            for (int j = 0; j < 4; j++)
                KPs[(tx * 4 + j) * P + ty * 4 + i] = s_[i][j];
        __syncthreads();

        // O += P @ V  (4x4 per thread; rows = queries ty*4.., cols = dh tx*4..)
#pragma unroll
        for (int c = 0; c < 64; c++) {
            float a[4], bv[4];
            *(float4*)a  = *(const float4*)(KPs + c * P + ty * 4);
            *(float4*)bv = *(const float4*)(Vs + c * P + tx * 4);
#pragma unroll
            for (int i = 0; i < 4; i++)
#pragma unroll
                for (int j = 0; j < 4; j++)
                    o_[i][j] = fmaf(a[i], bv[j], o_[i][j]);
        }
    }

    // normalize & write context in [B*S, D] layout (col = h*64 + d)
#pragma unroll
    for (int i = 0; i < 4; i++) {
        const int qg  = q0 + ty * 4 + i;
        const float inv = 1.0f / l_[i];
        float4 v = make_float4(o_[i][0] * inv, o_[i][1] * inv,
                               o_[i][2] * inv, o_[i][3] * inv);
        *(float4*)(g_Ctx + ((size_t)(b * SEQ) + qg) * D_MODEL + h * HDIM + tx * 4) = v;
    }
}

// =================================================================================
// Launch: three plain kernel launches, nothing else.
// =================================================================================
extern "C" void kernel_launch(void* const* d_in, const int* in_sizes, int n_in,
                              void* d_out, int out_size)
{
    const float* x  = (const float*)d_in[0];
    const float* Wq = (const float*)d_in[1];
    const float* Wk = (const float*)d_in[2];
    const float* Wv = (const float*)d_in[3];
    const float* Wo = (const float*)d_in[4];
    float* out = (float*)d_out;

    qkv_gemm_kernel<<<dim3(D_MODEL / 128, NROWS / 128, 3), 256>>>(x, Wq, Wk, Wv);

    attn_kernel<<<dim3(SEQ / 64, NHEADS, BATCH), 256>>>();

    out_gemm_kernel<<<dim3(D_MODEL / 128, NROWS / 128), 256>>>(Wo, out);
}

// round 4
// speedup vs baseline: 1.0671x; 1.0671x over previous
#include <cuda_runtime.h>
#include <cstdint>

#define D_MODEL 1024
#define NHEADS  16
#define HDIM    64
#define BATCH   2
#define SEQ     2048
#define NROWS   (BATCH * SEQ)   // 4096

// ---------------- scratch (static device globals; no allocations) ----------------
__device__ float g_Q[BATCH * NHEADS * SEQ * HDIM];    // [B,H,S,Dh]
__device__ float g_K[BATCH * NHEADS * SEQ * HDIM];
__device__ float g_V[BATCH * NHEADS * SEQ * HDIM];
__device__ float g_Ctx[NROWS * D_MODEL];              // [B*S, D]

// ---------------- tf32 helpers ----------------
__device__ __forceinline__ uint32_t f32_to_tf32(float x) {
    uint32_t r;
    asm("cvt.rna.tf32.f32 %0, %1;" : "=r"(r) : "f"(x));
    return r;
}

__device__ __forceinline__ void mma_tf32(float* c,
    uint32_t a0, uint32_t a1, uint32_t a2, uint32_t a3,
    uint32_t b0, uint32_t b1)
{
    asm volatile(
        "mma.sync.aligned.m16n8k8.row.col.f32.tf32.tf32.f32 "
        "{%0,%1,%2,%3}, {%4,%5,%6,%7}, {%8,%9}, {%0,%1,%2,%3};\n"
        : "+f"(c[0]), "+f"(c[1]), "+f"(c[2]), "+f"(c[3])
        : "r"(a0), "r"(a1), "r"(a2), "r"(a3), "r"(b0), "r"(b1));
}

// =================================================================================
// 3xTF32 tensor-core GEMM: C[4096x1024] = A @ W[1024x1024].
// Block tile 128x128, BK=16, 256 threads = 8 warps (2x4), warp tile 64x32.
// A/W split into tf32 hi+lo at smem-store time; 3 MMAs (hh, lh, hl) per unit.
// QKV=1: A=x, W selected by blockIdx.z, output scattered to g_Q/g_K/g_V [B,H,S,Dh].
// QKV=0: A=g_Ctx, W=W0, plain row-major output to Cout.
// =================================================================================
template <int QKV>
__global__ __launch_bounds__(256) void tf32_gemm(
    const float* __restrict__ Ain,
    const float* __restrict__ W0, const float* __restrict__ W1,
    const float* __restrict__ W2, float* __restrict__ Cout)
{
    constexpr int PA = 132;   // pitch for [k][m] A tiles
    __shared__ __align__(16) uint32_t Ah[16 * PA];
    __shared__ __align__(16) uint32_t Al[16 * PA];
    __shared__ __align__(16) uint32_t Bh[16 * PA];
    __shared__ __align__(16) uint32_t Bl[16 * PA];

    const float* A;
    const float* W;
    float* C;
    if (QKV) {
        A = Ain;
        W = (blockIdx.z == 0) ? W0 : (blockIdx.z == 1) ? W1 : W2;
        C = (blockIdx.z == 0) ? g_Q : (blockIdx.z == 1) ? g_K : g_V;
    } else {
        A = g_Ctx;
        W = W0;
        C = Cout;
    }

    const int t    = threadIdx.x;
    const int lane = t & 31;
    const int wid  = t >> 5;
    const int g    = lane >> 2;      // 0..7
    const int tq   = lane & 3;       // 0..3
    const int wm   = (wid & 1) * 64; // warp m offset in tile
    const int wn   = (wid >> 1) * 32;// warp n offset in tile
    const int m0   = blockIdx.y * 128;
    const int n0   = blockIdx.x * 128;

    // gmem slices for the cooperative tile loads
    const int ar = t >> 1;             // A row within tile: 0..127
    const int ac = (t & 1) * 8;        // A col base: 0 or 8
    const int br = t >> 4;             // B row (k) within tile: 0..15
    const int bc = (t & 15) * 8;       // B col base: 0..120
    const float* Ag = A + (size_t)(m0 + ar) * D_MODEL + ac;
    const float* Bg = W + (size_t)br * D_MODEL + n0 + bc;

    float acc[4][4][4];
#pragma unroll
    for (int mf = 0; mf < 4; mf++)
#pragma unroll
        for (int nf = 0; nf < 4; nf++)
#pragma unroll
            for (int r = 0; r < 4; r++) acc[mf][nf][r] = 0.0f;

    // prologue: load tile 0 into regs
    float4 pa0 = *(const float4*)(Ag);
    float4 pa1 = *(const float4*)(Ag + 4);
    float4 pb0 = *(const float4*)(Bg);
    float4 pb1 = *(const float4*)(Bg + 4);

    constexpr int NIT = D_MODEL / 16;   // 64
    for (int it = 0; it < NIT; ++it) {
        // split current regs and store to smem
        {
            float av[8] = {pa0.x, pa0.y, pa0.z, pa0.w, pa1.x, pa1.y, pa1.z, pa1.w};
#pragma unroll
            for (int i = 0; i < 8; i++) {
                uint32_t hi = f32_to_tf32(av[i]);
                uint32_t lo = f32_to_tf32(av[i] - __uint_as_float(hi));
                Ah[(ac + i) * PA + ar] = hi;
                Al[(ac + i) * PA + ar] = lo;
            }
            float bv[8] = {pb0.x, pb0.y, pb0.z, pb0.w, pb1.x, pb1.y, pb1.z, pb1.w};
            uint32_t bh[8], bl[8];
#pragma unroll
            for (int i = 0; i < 8; i++) {
                bh[i] = f32_to_tf32(bv[i]);
                bl[i] = f32_to_tf32(bv[i] - __uint_as_float(bh[i]));
            }
            *(uint4*)&Bh[br * PA + bc]     = make_uint4(bh[0], bh[1], bh[2], bh[3]);
            *(uint4*)&Bh[br * PA + bc + 4] = make_uint4(bh[4], bh[5], bh[6], bh[7]);
            *(uint4*)&Bl[br * PA + bc]     = make_uint4(bl[0], bl[1], bl[2], bl[3]);
            *(uint4*)&Bl[br * PA + bc + 4] = make_uint4(bl[4], bl[5], bl[6], bl[7]);
        }
        __syncthreads();

        // prefetch next tile (latency hidden behind compute below)
        if (it + 1 < NIT) {
            const int ko = (it + 1) * 16;
            pa0 = *(const float4*)(Ag + ko);
            pa1 = *(const float4*)(Ag + ko + 4);
            pb0 = *(const float4*)(Bg + (size_t)ko * D_MODEL);
            pb1 = *(const float4*)(Bg + (size_t)ko * D_MODEL + 4);
        }

        // compute: 2 k-fragments of 8
#pragma unroll
        for (int kf = 0; kf < 2; ++kf) {
            const int kb = kf * 8;
            uint32_t ah[4][4], al2[4][4], bhf[4][2], blf[4][2];
#pragma unroll
            for (int mf = 0; mf < 4; mf++) {
                const int ma = wm + mf * 16;
                ah[mf][0]  = Ah[(kb + tq)     * PA + ma + g];
                ah[mf][1]  = Ah[(kb + tq)     * PA + ma + g + 8];
                ah[mf][2]  = Ah[(kb + tq + 4) * PA + ma + g];
                ah[mf][3]  = Ah[(kb + tq + 4) * PA + ma + g + 8];
                al2[mf][0] = Al[(kb + tq)     * PA + ma + g];
                al2[mf][1] = Al[(kb + tq)     * PA + ma + g + 8];
                al2[mf][2] = Al[(kb + tq + 4) * PA + ma + g];
                al2[mf][3] = Al[(kb + tq + 4) * PA + ma + g + 8];
            }
#pragma unroll
            for (int nf = 0; nf < 4; nf++) {
                const int na = wn + nf * 8 + g;
                bhf[nf][0] = Bh[(kb + tq)     * PA + na];
                bhf[nf][1] = Bh[(kb + tq + 4) * PA + na];
                blf[nf][0] = Bl[(kb + tq)     * PA + na];
                blf[nf][1] = Bl[(kb + tq + 4) * PA + na];
            }
            // pass 1: hi*hi
#pragma unroll
            for (int mf = 0; mf < 4; mf++)
#pragma unroll
                for (int nf = 0; nf < 4; nf++)
                    mma_tf32(acc[mf][nf], ah[mf][0], ah[mf][1], ah[mf][2], ah[mf][3],
                             bhf[nf][0], bhf[nf][1]);
            // pass 2: lo*hi
#pragma unroll
            for (int mf = 0; mf < 4; mf++)
#pragma unroll
                for (int nf = 0; nf < 4; nf++)
                    mma_tf32(acc[mf][nf], al2[mf][0], al2[mf][1], al2[mf][2], al2[mf][3],
                             bhf[nf][0], bhf[nf][1]);
            // pass 3: hi*lo
#pragma unroll
            for (int mf = 0; mf < 4; mf++)
#pragma unroll
                for (int nf = 0; nf < 4; nf++)
                    mma_tf32(acc[mf][nf], ah[mf][0], ah[mf][1], ah[mf][2], ah[mf][3],
                             blf[nf][0], blf[nf][1]);
        }
        __syncthreads();
    }

    // epilogue: c0=(g,2tq) c1=(g,2tq+1) c2=(g+8,2tq) c3=(g+8,2tq+1) per frag
#pragma unroll
    for (int mf = 0; mf < 4; mf++) {
#pragma unroll
        for (int nf = 0; nf < 4; nf++) {
            const int n = n0 + wn + nf * 8 + 2 * tq;
#pragma unroll
            for (int half = 0; half < 2; half++) {
                const int m = m0 + wm + mf * 16 + g + half * 8;
                const float c0 = acc[mf][nf][half * 2 + 0];
                const float c1 = acc[mf][nf][half * 2 + 1];
                if (QKV) {
                    const int b  = m >> 11;
                    const int s  = m & (SEQ - 1);
                    const int h  = n >> 6;
                    const int dd = n & (HDIM - 1);
                    float2* p = (float2*)&C[(((size_t)(b * NHEADS + h)) * SEQ + s) * HDIM + dd];
                    *p = make_float2(c0, c1);
                } else {
                    float2* p = (float2*)&C[(size_t)m * D_MODEL + n];
                    *p = make_float2(c0, c1);
                }
            }
        }
    }
}

// =================================================================================
// Causal flash attention, fp32 SIMT. One block = 64 queries of one (b,h).
// 256 threads as 16x16; 4x4 micro-tiles. Static 48KB smem; Ps aliases Ks.
// Heavy query tiles launch first (qt reversed) for better wave packing.
// =================================================================================
__global__ __launch_bounds__(256) void attn_kernel()
{
    constexpr int P = 64;
    __shared__ float Qs[64 * P];                // [d][q]
    __shared__ float KPs[64 * P];               // K as [d][c], then probs as [c][r]
    __shared__ float Vs[64 * P];                // [c][d]

    const int t  = threadIdx.x;
    const int tx = t & 15;
    const int ty = t >> 4;
    const int qt = (int)gridDim.x - 1 - (int)blockIdx.x;   // heavy tiles first
    const int h  = blockIdx.y;
    const int b  = blockIdx.z;
    const int bh = b * NHEADS + h;
    const float* Qb = g_Q + (size_t)bh * SEQ * HDIM;
    const float* Kb = g_K + (size_t)bh * SEQ * HDIM;
    const float* Vb = g_V + (size_t)bh * SEQ * HDIM;
    const int q0 = qt * 64;

#pragma unroll
    for (int i = 0; i < 4; i++) {
        int idx = t + i * 256;
        int r   = idx >> 4;
        int c4  = (idx & 15) * 4;
        float4 v = *(const float4*)(Qb + (size_t)(q0 + r) * HDIM + c4);
        Qs[(c4 + 0) * P + r] = v.x;
        Qs[(c4 + 1) * P + r] = v.y;
        Qs[(c4 + 2) * P + r] = v.z;
        Qs[(c4 + 3) * P + r] = v.w;
    }

    float m_[4], l_[4], o_[4][4];
#pragma unroll
    for (int i = 0; i < 4; i++) {
        m_[i] = -1e30f;
        l_[i] = 0.0f;
#pragma unroll
        for (int j = 0; j < 4; j++) o_[i][j] = 0.0f;
    }

    for (int jt = 0; jt <= qt; jt++) {
        __syncthreads();
        const float* Kt = Kb + (size_t)jt * 64 * HDIM;
        const float* Vt = Vb + (size_t)jt * 64 * HDIM;
#pragma unroll
        for (int i = 0; i < 4; i++) {
            int idx = t + i * 256;
            int r   = idx >> 4;
            int c4  = (idx & 15) * 4;
            float4 kv = *(const float4*)(Kt + (size_t)r * HDIM + c4);
            KPs[(c4 + 0) * P + r] = kv.x;
            KPs[(c4 + 1) * P + r] = kv.y;
            KPs[(c4 + 2) * P + r] = kv.z;
            KPs[(c4 + 3) * P + r] = kv.w;
            *(float4*)(Vs + r * P + c4) = *(const float4*)(Vt + (size_t)r * HDIM + c4);
        }
        __syncthreads();

        float s_[4][4];
#pragma unroll
        for (int i = 0; i < 4; i++)
#pragma unroll
            for (int j = 0; j < 4; j++) s_[i][j] = 0.0f;
#pragma unroll
        for (int kk = 0; kk < 64; kk++) {
            float a[4], bv[4];
            *(float4*)a  = *(const float4*)(Qs + kk * P + ty * 4);
            *(float4*)bv = *(const float4*)(KPs + kk * P + tx * 4);
#pragma unroll
            for (int i = 0; i < 4; i++)
#pragma unroll
                for (int j = 0; j < 4; j++)
                    s_[i][j] = fmaf(a[i], bv[j], s_[i][j]);
        }
        __syncthreads();   // K reads complete before probs overwrite KPs

        const bool diag = (jt == qt);
#pragma unroll
        for (int i = 0; i < 4; i++) {
            const int qg = q0 + ty * 4 + i;
#pragma unroll
            for (int j = 0; j < 4; j++) {
                float v = s_[i][j] * 0.125f;       // 1/sqrt(64)
                const int kg = jt * 64 + tx * 4 + j;
                if (diag && kg > qg) v = -1e30f;
                s_[i][j] = v;
            }
        }

#pragma unroll
        for (int i = 0; i < 4; i++) {
            float tm = fmaxf(fmaxf(s_[i][0], s_[i][1]), fmaxf(s_[i][2], s_[i][3]));
#pragma unroll
            for (int off = 8; off > 0; off >>= 1)
                tm = fmaxf(tm, __shfl_xor_sync(0xffffffffu, tm, off));
            const float nm    = fmaxf(m_[i], tm);
            const float alpha = __expf(m_[i] - nm);
            float rs = 0.0f;
#pragma unroll
            for (int j = 0; j < 4; j++) {
                float p = __expf(s_[i][j] - nm);
                s_[i][j] = p;
                rs += p;
            }
#pragma unroll
            for (int off = 8; off > 0; off >>= 1)
                rs += __shfl_xor_sync(0xffffffffu, rs, off);
            l_[i] = l_[i] * alpha + rs;
            m_[i] = nm;
#pragma unroll
            for (int j = 0; j < 4; j++) o_[i][j] *= alpha;
        }

#pragma unroll
        for (int i = 0; i < 4; i++)
#pragma unroll
            for (int j = 0; j < 4; j++)
                KPs[(tx * 4 + j) * P + ty * 4 + i] = s_[i][j];
        __syncthreads();

#pragma unroll
        for (int c = 0; c < 64; c++) {
            float a[4], bv[4];
            *(float4*)a  = *(const float4*)(KPs + c * P + ty * 4);
            *(float4*)bv = *(const float4*)(Vs + c * P + tx * 4);
#pragma unroll
            for (int i = 0; i < 4; i++)
#pragma unroll
                for (int j = 0; j < 4; j++)
                    o_[i][j] = fmaf(a[i], bv[j], o_[i][j]);
        }
    }

#pragma unroll
    for (int i = 0; i < 4; i++) {
        const int qg  = q0 + ty * 4 + i;
        const float inv = 1.0f / l_[i];
        float4 v = make_float4(o_[i][0] * inv, o_[i][1] * inv,
                               o_[i][2] * inv, o_[i][3] * inv);
        *(float4*)(g_Ctx + ((size_t)(b * SEQ) + qg) * D_MODEL + h * HDIM + tx * 4) = v;
    }
}

// =================================================================================
// Launch: three plain kernel launches.
// =================================================================================
extern "C" void kernel_launch(void* const* d_in, const int* in_sizes, int n_in,
                              void* d_out, int out_size)
{
    const float* x  = (const float*)d_in[0];
    const float* Wq = (const float*)d_in[1];
    const float* Wk = (const float*)d_in[2];
    const float* Wv = (const float*)d_in[3];
    const float* Wo = (const float*)d_in[4];
    float* out = (float*)d_out;

    tf32_gemm<1><<<dim3(D_MODEL / 128, NROWS / 128, 3), 256>>>(x, Wq, Wk, Wv, nullptr);

    attn_kernel<<<dim3(SEQ / 64, NHEADS, BATCH), 256>>>();

    tf32_gemm<0><<<dim3(D_MODEL / 128, NROWS / 128, 1), 256>>>(nullptr, Wo, nullptr, nullptr, out);
}

// round 6
// speedup vs baseline: 1.4517x; 1.3605x over previous
#include <cuda_runtime.h>
#include <cuda_bf16.h>
#include <cstdint>

#define D_MODEL 1024
#define NHEADS  16
#define HDIM    64
#define BATCH   2
#define SEQ     2048
#define NROWS   (BATCH * SEQ)   // 4096

// ---------------- scratch (static device globals; no allocations) ----------------
__device__ float g_Q[BATCH * NHEADS * SEQ * HDIM];    // [B,H,S,Dh]
__device__ float g_K[BATCH * NHEADS * SEQ * HDIM];
__device__ float g_V[BATCH * NHEADS * SEQ * HDIM];
__device__ float g_Ctx[NROWS * D_MODEL];              // [B*S, D]

// ---------------- helpers ----------------
__device__ __forceinline__ uint32_t pack_bf16_hi(float x0, float x1, float& r0, float& r1) {
    __nv_bfloat16 h0 = __float2bfloat16(x0);
    __nv_bfloat16 h1 = __float2bfloat16(x1);
    r0 = x0 - __bfloat162float(h0);
    r1 = x1 - __bfloat162float(h1);
    return ((uint32_t)__bfloat16_as_ushort(h1) << 16) | (uint32_t)__bfloat16_as_ushort(h0);
}
__device__ __forceinline__ uint32_t pack_bf16(float x0, float x1) {
    __nv_bfloat16 h0 = __float2bfloat16(x0);
    __nv_bfloat16 h1 = __float2bfloat16(x1);
    return ((uint32_t)__bfloat16_as_ushort(h1) << 16) | (uint32_t)__bfloat16_as_ushort(h0);
}

__device__ __forceinline__ void ldmatrix_x4(uint32_t& r0, uint32_t& r1,
                                            uint32_t& r2, uint32_t& r3, uint32_t addr) {
    asm volatile("ldmatrix.sync.aligned.m8n8.x4.shared.b16 {%0,%1,%2,%3}, [%4];"
                 : "=r"(r0), "=r"(r1), "=r"(r2), "=r"(r3) : "r"(addr));
}

__device__ __forceinline__ void mma_bf16(float* c,
    uint32_t a0, uint32_t a1, uint32_t a2, uint32_t a3,
    uint32_t b0, uint32_t b1)
{
    asm volatile(
        "mma.sync.aligned.m16n8k16.row.col.f32.bf16.bf16.f32 "
        "{%0,%1,%2,%3}, {%4,%5,%6,%7}, {%8,%9}, {%0,%1,%2,%3};\n"
        : "+f"(c[0]), "+f"(c[1]), "+f"(c[2]), "+f"(c[3])
        : "r"(a0), "r"(a1), "r"(a2), "r"(a3), "r"(b0), "r"(b1));
}

// =================================================================================
// bf16-split (hh+lh+hl) tensor-core GEMM: C[4096x1024] = A @ W[1024x1024].
// Block tile 128x128, BK=16, 256 threads = 8 warps (2x4), warp tile 64x32.
// A in smem as [m][k] bf16 rows (16 bf16 = 32B, padded to 48B) for ldmatrix.x4.
// B in smem as [k/2][n] bf16x2 (k-pairs packed), pitch 136 words: conflict-free.
// QKV=1: A=x, W by blockIdx.z, output scattered to g_Q/g_K/g_V [B,H,S,Dh].
// QKV=0: A=g_Ctx, W=W0, row-major output to Cout.
// =================================================================================
template <int QKV>
__global__ __launch_bounds__(256) void bf16_gemm(
    const float* __restrict__ Ain,
    const float* __restrict__ W0, const float* __restrict__ W1,
    const float* __restrict__ W2, float* __restrict__ Cout)
{
    constexpr int AP = 12;    // words per A row (8 used + 4 pad = 48B)
    constexpr int BP = 136;   // words per B k2-row (128 + 8 pad)
    __shared__ __align__(16) uint32_t Ah[128 * AP];
    __shared__ __align__(16) uint32_t Al[128 * AP];
    __shared__ __align__(16) uint32_t Bh[8 * BP];
    __shared__ __align__(16) uint32_t Bl[8 * BP];

    const float* A;
    const float* W;
    float* C;
    if (QKV) {
        A = Ain;
        W = (blockIdx.z == 0) ? W0 : (blockIdx.z == 1) ? W1 : W2;
        C = (blockIdx.z == 0) ? g_Q : (blockIdx.z == 1) ? g_K : g_V;
    } else {
        A = g_Ctx;
        W = W0;
        C = Cout;
    }

    const int t    = threadIdx.x;
    const int lane = t & 31;
    const int wid  = t >> 5;
    const int g    = lane >> 2;       // 0..7
    const int tq   = lane & 3;        // 0..3
    const int wm   = (wid & 1) * 64;
    const int wn   = (wid >> 1) * 32;
    const int m0   = blockIdx.y * 128;
    const int n0   = blockIdx.x * 128;

    // A gmem mapping: thread covers (row ar, k ac..ac+7)
    const int ar  = t >> 1;           // 0..127
    const int ac  = (t & 1) * 8;      // 0 or 8
    const int ac2 = (t & 1) * 4;      // word offset in packed row
    // B gmem mapping: thread covers (k rows 2*bk2, 2*bk2+1, n bn..bn+3)
    const int bk2 = t >> 5;           // 0..7
    const int bn  = (t & 31) * 4;     // 0..124
    const float* Ag  = A + (size_t)(m0 + ar) * D_MODEL + ac;
    const float* Bg0 = W + (size_t)(2 * bk2) * D_MODEL + n0 + bn;

    // ldmatrix source address (fixed per thread, varies by mf)
    const int lrow = lane & 15;       // matrix row (m offset)
    const int lkh  = (lane >> 4) * 4; // k-half word offset

    float acc[4][4][4];
#pragma unroll
    for (int mf = 0; mf < 4; mf++)
#pragma unroll
        for (int nf = 0; nf < 4; nf++)
#pragma unroll
            for (int r = 0; r < 4; r++) acc[mf][nf][r] = 0.0f;

    // prologue: prefetch tile 0
    float4 pa0 = *(const float4*)(Ag);
    float4 pa1 = *(const float4*)(Ag + 4);
    float4 pb0 = *(const float4*)(Bg0);
    float4 pb1 = *(const float4*)(Bg0 + D_MODEL);

    const uint32_t ah_base = (uint32_t)__cvta_generic_to_shared(Ah);
    const uint32_t al_base = (uint32_t)__cvta_generic_to_shared(Al);

    constexpr int NIT = D_MODEL / 16;   // 64
    for (int it = 0; it < NIT; ++it) {
        // ---- split + store current tile ----
        {
            float av[8] = {pa0.x, pa0.y, pa0.z, pa0.w, pa1.x, pa1.y, pa1.z, pa1.w};
            uint32_t hi[4], lo[4];
#pragma unroll
            for (int i = 0; i < 4; i++) {
                float r0, r1;
                hi[i] = pack_bf16_hi(av[2 * i], av[2 * i + 1], r0, r1);
                lo[i] = pack_bf16(r0, r1);
            }
            *(uint4*)&Ah[ar * AP + ac2] = make_uint4(hi[0], hi[1], hi[2], hi[3]);
            *(uint4*)&Al[ar * AP + ac2] = make_uint4(lo[0], lo[1], lo[2], lo[3]);

            const float b0v[4] = {pb0.x, pb0.y, pb0.z, pb0.w};
            const float b1v[4] = {pb1.x, pb1.y, pb1.z, pb1.w};
            uint32_t bhi[4], blo[4];
#pragma unroll
            for (int j = 0; j < 4; j++) {
                float r0, r1;
                bhi[j] = pack_bf16_hi(b0v[j], b1v[j], r0, r1);
                blo[j] = pack_bf16(r0, r1);
            }
            *(uint4*)&Bh[bk2 * BP + bn] = make_uint4(bhi[0], bhi[1], bhi[2], bhi[3]);
            *(uint4*)&Bl[bk2 * BP + bn] = make_uint4(blo[0], blo[1], blo[2], blo[3]);
        }
        __syncthreads();

        // ---- prefetch next tile ----
        if (it + 1 < NIT) {
            const int ko = (it + 1) * 16;
            pa0 = *(const float4*)(Ag + ko);
            pa1 = *(const float4*)(Ag + ko + 4);
            pb0 = *(const float4*)(Bg0 + (size_t)ko * D_MODEL);
            pb1 = *(const float4*)(Bg0 + (size_t)(ko + 1) * D_MODEL);
        }

        // ---- load fragments ----
        uint32_t ah[4][4], al[4][4], bh[4][2], bl[4][2];
#pragma unroll
        for (int mf = 0; mf < 4; mf++) {
            const uint32_t off = (uint32_t)(((wm + mf * 16 + lrow) * AP + lkh) * 4);
            ldmatrix_x4(ah[mf][0], ah[mf][1], ah[mf][2], ah[mf][3], ah_base + off);
            ldmatrix_x4(al[mf][0], al[mf][1], al[mf][2], al[mf][3], al_base + off);
        }
#pragma unroll
        for (int nf = 0; nf < 4; nf++) {
            const int na = wn + nf * 8 + g;
            bh[nf][0] = Bh[tq * BP + na];
            bh[nf][1] = Bh[(tq + 4) * BP + na];
            bl[nf][0] = Bl[tq * BP + na];
            bl[nf][1] = Bl[(tq + 4) * BP + na];
        }

        // ---- 3 passes: hh, lh, hl ----
#pragma unroll
        for (int mf = 0; mf < 4; mf++)
#pragma unroll
            for (int nf = 0; nf < 4; nf++)
                mma_bf16(acc[mf][nf], ah[mf][0], ah[mf][1], ah[mf][2], ah[mf][3],
                         bh[nf][0], bh[nf][1]);
#pragma unroll
        for (int mf = 0; mf < 4; mf++)
#pragma unroll
            for (int nf = 0; nf < 4; nf++)
                mma_bf16(acc[mf][nf], al[mf][0], al[mf][1], al[mf][2], al[mf][3],
                         bh[nf][0], bh[nf][1]);
#pragma unroll
        for (int mf = 0; mf < 4; mf++)
#pragma unroll
            for (int nf = 0; nf < 4; nf++)
                mma_bf16(acc[mf][nf], ah[mf][0], ah[mf][1], ah[mf][2], ah[mf][3],
                         bl[nf][0], bl[nf][1]);
        __syncthreads();
    }

    // ---- epilogue: c0=(g,2tq) c1=(g,2tq+1) c2=(g+8,2tq) c3=(g+8,2tq+1) ----
#pragma unroll
    for (int mf = 0; mf < 4; mf++) {
#pragma unroll
        for (int nf = 0; nf < 4; nf++) {
            const int n = n0 + wn + nf * 8 + 2 * tq;
#pragma unroll
            for (int half = 0; half < 2; half++) {
                const int m = m0 + wm + mf * 16 + g + half * 8;
                const float c0 = acc[mf][nf][half * 2 + 0];
                const float c1 = acc[mf][nf][half * 2 + 1];
                if (QKV) {
                    const int b  = m >> 11;
                    const int s  = m & (SEQ - 1);
                    const int h  = n >> 6;
                    const int dd = n & (HDIM - 1);
                    *(float2*)&C[(((size_t)(b * NHEADS + h)) * SEQ + s) * HDIM + dd] =
                        make_float2(c0, c1);
                } else {
                    *(float2*)&C[(size_t)m * D_MODEL + n] = make_float2(c0, c1);
                }
            }
        }
    }
}

// =================================================================================
// Causal flash attention, fp32 SIMT (unchanged, verified). One block = 64 queries.
// =================================================================================
__global__ __launch_bounds__(256) void attn_kernel()
{
    constexpr int P = 64;
    __shared__ float Qs[64 * P];
    __shared__ float KPs[64 * P];
    __shared__ float Vs[64 * P];

    const int t  = threadIdx.x;
    const int tx = t & 15;
    const int ty = t >> 4;
    const int qt = (int)gridDim.x - 1 - (int)blockIdx.x;
    const int h  = blockIdx.y;
    const int b  = blockIdx.z;
    const int bh = b * NHEADS + h;
    const float* Qb = g_Q + (size_t)bh * SEQ * HDIM;
    const float* Kb = g_K + (size_t)bh * SEQ * HDIM;
    const float* Vb = g_V + (size_t)bh * SEQ * HDIM;
    const int q0 = qt * 64;

#pragma unroll
    for (int i = 0; i < 4; i++) {
        int idx = t + i * 256;
        int r   = idx >> 4;
        int c4  = (idx & 15) * 4;
        float4 v = *(const float4*)(Qb + (size_t)(q0 + r) * HDIM + c4);
        Qs[(c4 + 0) * P + r] = v.x;
        Qs[(c4 + 1) * P + r] = v.y;
        Qs[(c4 + 2) * P + r] = v.z;
        Qs[(c4 + 3) * P + r] = v.w;
    }

    float m_[4], l_[4], o_[4][4];
#pragma unroll
    for (int i = 0; i < 4; i++) {
        m_[i] = -1e30f;
        l_[i] = 0.0f;
#pragma unroll
        for (int j = 0; j < 4; j++) o_[i][j] = 0.0f;
    }

    for (int jt = 0; jt <= qt; jt++) {
        __syncthreads();
        const float* Kt = Kb + (size_t)jt * 64 * HDIM;
        const float* Vt = Vb + (size_t)jt * 64 * HDIM;
#pragma unroll
        for (int i = 0; i < 4; i++) {
            int idx = t + i * 256;
            int r   = idx >> 4;
            int c4  = (idx & 15) * 4;
            float4 kv = *(const float4*)(Kt + (size_t)r * HDIM + c4);
            KPs[(c4 + 0) * P + r] = kv.x;
            KPs[(c4 + 1) * P + r] = kv.y;
            KPs[(c4 + 2) * P + r] = kv.z;
            KPs[(c4 + 3) * P + r] = kv.w;
            *(float4*)(Vs + r * P + c4) = *(const float4*)(Vt + (size_t)r * HDIM + c4);
        }
        __syncthreads();

        float s_[4][4];
#pragma unroll
        for (int i = 0; i < 4; i++)
#pragma unroll
            for (int j = 0; j < 4; j++) s_[i][j] = 0.0f;
#pragma unroll
        for (int kk = 0; kk < 64; kk++) {
            float a[4], bv[4];
            *(float4*)a  = *(const float4*)(Qs + kk * P + ty * 4);
            *(float4*)bv = *(const float4*)(KPs + kk * P + tx * 4);
#pragma unroll
            for (int i = 0; i < 4; i++)
#pragma unroll
                for (int j = 0; j < 4; j++)
                    s_[i][j] = fmaf(a[i], bv[j], s_[i][j]);
        }
        __syncthreads();

        const bool diag = (jt == qt);
#pragma unroll
        for (int i = 0; i < 4; i++) {
            const int qg = q0 + ty * 4 + i;
#pragma unroll
            for (int j = 0; j < 4; j++) {
                float v = s_[i][j] * 0.125f;
                const int kg = jt * 64 + tx * 4 + j;
                if (diag && kg > qg) v = -1e30f;
                s_[i][j] = v;
            }
        }

#pragma unroll
        for (int i = 0; i < 4; i++) {
            float tm = fmaxf(fmaxf(s_[i][0], s_[i][1]), fmaxf(s_[i][2], s_[i][3]));
#pragma unroll
            for (int off = 8; off > 0; off >>= 1)
                tm = fmaxf(tm, __shfl_xor_sync(0xffffffffu, tm, off));
            const float nm    = fmaxf(m_[i], tm);
            const float alpha = __expf(m_[i] - nm);
            float rs = 0.0f;
#pragma unroll
            for (int j = 0; j < 4; j++) {
                float p = __expf(s_[i][j] - nm);
                s_[i][j] = p;
                rs += p;
            }
#pragma unroll
            for (int off = 8; off > 0; off >>= 1)
                rs += __shfl_xor_sync(0xffffffffu, rs, off);
            l_[i] = l_[i] * alpha + rs;
            m_[i] = nm;
#pragma unroll
            for (int j = 0; j < 4; j++) o_[i][j] *= alpha;
        }

#pragma unroll
        for (int i = 0; i < 4; i++)
#pragma unroll
            for (int j = 0; j < 4; j++)
                KPs[(tx * 4 + j) * P + ty * 4 + i] = s_[i][j];
        __syncthreads();

#pragma unroll
        for (int c = 0; c < 64; c++) {
            float a[4], bv[4];
            *(float4*)a  = *(const float4*)(KPs + c * P + ty * 4);
            *(float4*)bv = *(const float4*)(Vs + c * P + tx * 4);
#pragma unroll
            for (int i = 0; i < 4; i++)
#pragma unroll
                for (int j = 0; j < 4; j++)
                    o_[i][j] = fmaf(a[i], bv[j], o_[i][j]);
        }
    }

#pragma unroll
    for (int i = 0; i < 4; i++) {
        const int qg  = q0 + ty * 4 + i;
        const float inv = 1.0f / l_[i];
        float4 v = make_float4(o_[i][0] * inv, o_[i][1] * inv,
                               o_[i][2] * inv, o_[i][3] * inv);
        *(float4*)(g_Ctx + ((size_t)(b * SEQ) + qg) * D_MODEL + h * HDIM + tx * 4) = v;
    }
}

// =================================================================================
// Launch
// =================================================================================
extern "C" void kernel_launch(void* const* d_in, const int* in_sizes, int n_in,
                              void* d_out, int out_size)
{
    const float* x  = (const float*)d_in[0];
    const float* Wq = (const float*)d_in[1];
    const float* Wk = (const float*)d_in[2];
    const float* Wv = (const float*)d_in[3];
    const float* Wo = (const float*)d_in[4];
    float* out = (float*)d_out;

    bf16_gemm<1><<<dim3(D_MODEL / 128, NROWS / 128, 3), 256>>>(x, Wq, Wk, Wv, nullptr);

    attn_kernel<<<dim3(SEQ / 64, NHEADS, BATCH), 256>>>();

    bf16_gemm<0><<<dim3(D_MODEL / 128, NROWS / 128, 1), 256>>>(nullptr, Wo, nullptr, nullptr, out);
}

// round 7
// speedup vs baseline: 3.5109x; 2.4184x over previous
#include <cuda_runtime.h>
#include <cuda_bf16.h>
#include <cuda_fp16.h>
#include <cstdint>

#define D_MODEL 1024
#define NHEADS  16
#define HDIM    64
#define BATCH   2
#define SEQ     2048
#define NROWS   (BATCH * SEQ)   // 4096
#define QTILE   128

// ---------------- scratch (static device globals; no allocations) ----------------
__device__ __half g_Qh[BATCH * NHEADS * SEQ * HDIM];   // [B,H,S,Dh] fp16
__device__ __half g_Kh[BATCH * NHEADS * SEQ * HDIM];
__device__ __half g_Vh[BATCH * NHEADS * SEQ * HDIM];
__device__ float  g_Ctx[NROWS * D_MODEL];              // [B*S, D] fp32

// ---------------- helpers ----------------
__device__ __forceinline__ uint32_t pack_bf16_hi(float x0, float x1, float& r0, float& r1) {
    __nv_bfloat16 h0 = __float2bfloat16(x0);
    __nv_bfloat16 h1 = __float2bfloat16(x1);
    r0 = x0 - __bfloat162float(h0);
    r1 = x1 - __bfloat162float(h1);
    return ((uint32_t)__bfloat16_as_ushort(h1) << 16) | (uint32_t)__bfloat16_as_ushort(h0);
}
__device__ __forceinline__ uint32_t pack_bf16(float x0, float x1) {
    __nv_bfloat16 h0 = __float2bfloat16(x0);
    __nv_bfloat16 h1 = __float2bfloat16(x1);
    return ((uint32_t)__bfloat16_as_ushort(h1) << 16) | (uint32_t)__bfloat16_as_ushort(h0);
}
__device__ __forceinline__ uint32_t pack_f16(float x0, float x1) {
    __half2 h = __floats2half2_rn(make_float2(x0, x1).x == x0 ? x0 : x0, x1);
    // (construct directly)
    h = __floats2half2_rn(x0, x1);
    return *(uint32_t*)&h;
}

__device__ __forceinline__ void ldmatrix_x4(uint32_t& r0, uint32_t& r1,
                                            uint32_t& r2, uint32_t& r3, uint32_t addr) {
    asm volatile("ldmatrix.sync.aligned.m8n8.x4.shared.b16 {%0,%1,%2,%3}, [%4];"
                 : "=r"(r0), "=r"(r1), "=r"(r2), "=r"(r3) : "r"(addr));
}
__device__ __forceinline__ void ldmatrix_x4_trans(uint32_t& r0, uint32_t& r1,
                                                  uint32_t& r2, uint32_t& r3, uint32_t addr) {
    asm volatile("ldmatrix.sync.aligned.m8n8.x4.trans.shared.b16 {%0,%1,%2,%3}, [%4];"
                 : "=r"(r0), "=r"(r1), "=r"(r2), "=r"(r3) : "r"(addr));
}

__device__ __forceinline__ void mma_bf16(float* c,
    uint32_t a0, uint32_t a1, uint32_t a2, uint32_t a3,
    uint32_t b0, uint32_t b1)
{
    asm volatile(
        "mma.sync.aligned.m16n8k16.row.col.f32.bf16.bf16.f32 "
        "{%0,%1,%2,%3}, {%4,%5,%6,%7}, {%8,%9}, {%0,%1,%2,%3};\n"
        : "+f"(c[0]), "+f"(c[1]), "+f"(c[2]), "+f"(c[3])
        : "r"(a0), "r"(a1), "r"(a2), "r"(a3), "r"(b0), "r"(b1));
}
__device__ __forceinline__ void mma_f16(float* c,
    uint32_t a0, uint32_t a1, uint32_t a2, uint32_t a3,
    uint32_t b0, uint32_t b1)
{
    asm volatile(
        "mma.sync.aligned.m16n8k16.row.col.f32.f16.f16.f32 "
        "{%0,%1,%2,%3}, {%4,%5,%6,%7}, {%8,%9}, {%0,%1,%2,%3};\n"
        : "+f"(c[0]), "+f"(c[1]), "+f"(c[2]), "+f"(c[3])
        : "r"(a0), "r"(a1), "r"(a2), "r"(a3), "r"(b0), "r"(b1));
}

// =================================================================================
// bf16-split (hh+lh+hl) tensor-core GEMM (same structure as verified Round-6).
// QKV=1: A=x, W by blockIdx.z, output -> fp16 g_Qh/g_Kh/g_Vh in [B,H,S,Dh].
// QKV=0: A=g_Ctx, W=W0, fp32 row-major output to Cout.
// =================================================================================
template <int QKV>
__global__ __launch_bounds__(256) void bf16_gemm(
    const float* __restrict__ Ain,
    const float* __restrict__ W0, const float* __restrict__ W1,
    const float* __restrict__ W2, float* __restrict__ Cout)
{
    constexpr int AP = 12;
    constexpr int BP = 136;
    __shared__ __align__(16) uint32_t Ah[128 * AP];
    __shared__ __align__(16) uint32_t Al[128 * AP];
    __shared__ __align__(16) uint32_t Bh[8 * BP];
    __shared__ __align__(16) uint32_t Bl[8 * BP];

    const float* A;
    const float* W;
    __half* Ch = nullptr;
    float* Cf = nullptr;
    if (QKV) {
        A  = Ain;
        W  = (blockIdx.z == 0) ? W0 : (blockIdx.z == 1) ? W1 : W2;
        Ch = (blockIdx.z == 0) ? g_Qh : (blockIdx.z == 1) ? g_Kh : g_Vh;
    } else {
        A  = g_Ctx;
        W  = W0;
        Cf = Cout;
    }

    const int t    = threadIdx.x;
    const int lane = t & 31;
    const int wid  = t >> 5;
    const int g    = lane >> 2;
    const int tq   = lane & 3;
    const int wm   = (wid & 1) * 64;
    const int wn   = (wid >> 1) * 32;
    const int m0   = blockIdx.y * 128;
    const int n0   = blockIdx.x * 128;

    const int ar  = t >> 1;
    const int ac2 = (t & 1) * 4;
    const int bk2 = t >> 5;
    const int bn  = (t & 31) * 4;
    const float* Ag  = A + (size_t)(m0 + ar) * D_MODEL + (t & 1) * 8;
    const float* Bg0 = W + (size_t)(2 * bk2) * D_MODEL + n0 + bn;

    const int lrow = lane & 15;
    const int lkh  = (lane >> 4) * 4;

    float acc[4][4][4];
#pragma unroll
    for (int mf = 0; mf < 4; mf++)
#pragma unroll
        for (int nf = 0; nf < 4; nf++)
#pragma unroll
            for (int r = 0; r < 4; r++) acc[mf][nf][r] = 0.0f;

    float4 pa0 = *(const float4*)(Ag);
    float4 pa1 = *(const float4*)(Ag + 4);
    float4 pb0 = *(const float4*)(Bg0);
    float4 pb1 = *(const float4*)(Bg0 + D_MODEL);

    const uint32_t ah_base = (uint32_t)__cvta_generic_to_shared(Ah);
    const uint32_t al_base = (uint32_t)__cvta_generic_to_shared(Al);

    constexpr int NIT = D_MODEL / 16;
    for (int it = 0; it < NIT; ++it) {
        {
            float av[8] = {pa0.x, pa0.y, pa0.z, pa0.w, pa1.x, pa1.y, pa1.z, pa1.w};
            uint32_t hi[4], lo[4];
#pragma unroll
            for (int i = 0; i < 4; i++) {
                float r0, r1;
                hi[i] = pack_bf16_hi(av[2 * i], av[2 * i + 1], r0, r1);
                lo[i] = pack_bf16(r0, r1);
            }
            *(uint4*)&Ah[ar * AP + ac2] = make_uint4(hi[0], hi[1], hi[2], hi[3]);
            *(uint4*)&Al[ar * AP + ac2] = make_uint4(lo[0], lo[1], lo[2], lo[3]);

            const float b0v[4] = {pb0.x, pb0.y, pb0.z, pb0.w};
            const float b1v[4] = {pb1.x, pb1.y, pb1.z, pb1.w};
            uint32_t bhi[4], blo[4];
#pragma unroll
            for (int j = 0; j < 4; j++) {
                float r0, r1;
                bhi[j] = pack_bf16_hi(b0v[j], b1v[j], r0, r1);
                blo[j] = pack_bf16(r0, r1);
            }
            *(uint4*)&Bh[bk2 * BP + bn] = make_uint4(bhi[0], bhi[1], bhi[2], bhi[3]);
            *(uint4*)&Bl[bk2 * BP + bn] = make_uint4(blo[0], blo[1], blo[2], blo[3]);
        }
        __syncthreads();

        if (it + 1 < NIT) {
            const int ko = (it + 1) * 16;
            pa0 = *(const float4*)(Ag + ko);
            pa1 = *(const float4*)(Ag + ko + 4);
            pb0 = *(const float4*)(Bg0 + (size_t)ko * D_MODEL);
            pb1 = *(const float4*)(Bg0 + (size_t)(ko + 1) * D_MODEL);
        }

        uint32_t ah[4][4], al[4][4], bh[4][2], bl[4][2];
#pragma unroll
        for (int mf = 0; mf < 4; mf++) {
            const uint32_t off = (uint32_t)(((wm + mf * 16 + lrow) * AP + lkh) * 4);
            ldmatrix_x4(ah[mf][0], ah[mf][1], ah[mf][2], ah[mf][3], ah_base + off);
            ldmatrix_x4(al[mf][0], al[mf][1], al[mf][2], al[mf][3], al_base + off);
        }
#pragma unroll
        for (int nf = 0; nf < 4; nf++) {
            const int na = wn + nf * 8 + g;
            bh[nf][0] = Bh[tq * BP + na];
            bh[nf][1] = Bh[(tq + 4) * BP + na];
            bl[nf][0] = Bl[tq * BP + na];
            bl[nf][1] = Bl[(tq + 4) * BP + na];
        }

#pragma unroll
        for (int mf = 0; mf < 4; mf++)
#pragma unroll
            for (int nf = 0; nf < 4; nf++)
                mma_bf16(acc[mf][nf], ah[mf][0], ah[mf][1], ah[mf][2], ah[mf][3],
                         bh[nf][0], bh[nf][1]);
#pragma unroll
        for (int mf = 0; mf < 4; mf++)
#pragma unroll
            for (int nf = 0; nf < 4; nf++)
                mma_bf16(acc[mf][nf], al[mf][0], al[mf][1], al[mf][2], al[mf][3],
                         bh[nf][0], bh[nf][1]);
#pragma unroll
        for (int mf = 0; mf < 4; mf++)
#pragma unroll
            for (int nf = 0; nf < 4; nf++)
                mma_bf16(acc[mf][nf], ah[mf][0], ah[mf][1], ah[mf][2], ah[mf][3],
                         bl[nf][0], bl[nf][1]);
        __syncthreads();
    }

#pragma unroll
    for (int mf = 0; mf < 4; mf++) {
#pragma unroll
        for (int nf = 0; nf < 4; nf++) {
            const int n = n0 + wn + nf * 8 + 2 * tq;
#pragma unroll
            for (int half = 0; half < 2; half++) {
                const int m = m0 + wm + mf * 16 + g + half * 8;
                const float c0 = acc[mf][nf][half * 2 + 0];
                const float c1 = acc[mf][nf][half * 2 + 1];
                if (QKV) {
                    const int b  = m >> 11;
                    const int s  = m & (SEQ - 1);
                    const int h  = n >> 6;
                    const int dd = n & (HDIM - 1);
                    __half2 hv = __floats2half2_rn(c0, c1);
                    *(__half2*)&Ch[(((size_t)(b * NHEADS + h)) * SEQ + s) * HDIM + dd] = hv;
                } else {
                    *(float2*)&Cf[(size_t)m * D_MODEL + n] = make_float2(c0, c1);
                }
            }
        }
    }
}

// =================================================================================
// fp16 tensor-core causal flash attention.
// Block = 128 queries of one (b,h); 8 warps, each owns 16 full rows (warp-local
// softmax). KV tiles 64x64 fp16 in smem (pitch 36 words, conflict-free ldmatrix).
// QK^T: A=Q frags (regs), B=K via ldmatrix.x4. PV: A=P packed from S regs
// (no smem round trip), B=V via ldmatrix.x4.trans. fp32 accum + online softmax.
// =================================================================================
__global__ __launch_bounds__(256) void attn_mma_kernel()
{
    constexpr int KP = 36;   // words per kv row (32 used + 4 pad)
    __shared__ __align__(16) uint32_t Ks[64 * KP];
    __shared__ __align__(16) uint32_t Vs[64 * KP];

    const int t    = threadIdx.x;
    const int lane = t & 31;
    const int wid  = t >> 5;
    const int g    = lane >> 2;      // 0..7
    const int tq   = lane & 3;       // 0..3
    const int quad = lane >> 3;      // 0..3 (ldmatrix matrix id)
    const int idx8 = lane & 7;       // row within matrix

    const int qt = (int)gridDim.x - 1 - (int)blockIdx.x;   // heavy first
    const int h  = blockIdx.y;
    const int b  = blockIdx.z;
    const int bh = b * NHEADS + h;
    const __half* Qb = g_Qh + (size_t)bh * SEQ * HDIM;
    const __half* Kb = g_Kh + (size_t)bh * SEQ * HDIM;
    const __half* Vb = g_Vh + (size_t)bh * SEQ * HDIM;
    const int q0  = qt * QTILE;
    const int wr0 = q0 + wid * 16;   // warp's first query row

    // ---- Q fragments (persistent in registers) ----
    uint32_t qa[4][4];
#pragma unroll
    for (int kb = 0; kb < 4; kb++) {
        const int col = kb * 16 + 2 * tq;
        qa[kb][0] = *(const uint32_t*)&Qb[(size_t)(wr0 + g) * HDIM + col];
        qa[kb][1] = *(const uint32_t*)&Qb[(size_t)(wr0 + g + 8) * HDIM + col];
        qa[kb][2] = *(const uint32_t*)&Qb[(size_t)(wr0 + g) * HDIM + col + 8];
        qa[kb][3] = *(const uint32_t*)&Qb[(size_t)(wr0 + g + 8) * HDIM + col + 8];
    }

    float m0 = -1e30f, m1 = -1e30f, l0 = 0.0f, l1 = 0.0f;
    float o[8][4];
#pragma unroll
    for (int nf = 0; nf < 8; nf++)
#pragma unroll
        for (int r = 0; r < 4; r++) o[nf][r] = 0.0f;

    const uint32_t ks_base = (uint32_t)__cvta_generic_to_shared(Ks);
    const uint32_t vs_base = (uint32_t)__cvta_generic_to_shared(Vs);

    // K/V gmem->smem mapping: thread covers row lr, words lc..lc+3 and lc+16..lc+19
    const int lr = t >> 2;
    const int lc = (t & 3) * 4;

    const int njt = (q0 + QTILE) / 64;   // 2*qt + 2
    for (int jt = 0; jt < njt; jt++) {
        __syncthreads();
        const __half* Kt = Kb + (size_t)jt * 64 * HDIM;
        const __half* Vt = Vb + (size_t)jt * 64 * HDIM;
        *(uint4*)&Ks[lr * KP + lc]      = *(const uint4*)&Kt[lr * HDIM + lc * 2];
        *(uint4*)&Ks[lr * KP + lc + 16] = *(const uint4*)&Kt[lr * HDIM + (lc + 16) * 2];
        *(uint4*)&Vs[lr * KP + lc]      = *(const uint4*)&Vt[lr * HDIM + lc * 2];
        *(uint4*)&Vs[lr * KP + lc + 16] = *(const uint4*)&Vt[lr * HDIM + (lc + 16) * 2];
        __syncthreads();

        if (jt * 64 > wr0 + 15) continue;   // entire warp tile masked

        // ---- S = Q @ K^T ----
        float c[8][4];
#pragma unroll
        for (int nf = 0; nf < 8; nf++)
#pragma unroll
            for (int r = 0; r < 4; r++) c[nf][r] = 0.0f;

#pragma unroll
        for (int kb = 0; kb < 4; kb++) {
#pragma unroll
            for (int np = 0; np < 4; np++) {
                // lane address: matrices (np*16 rows block) x (kb k-block)
                const int krow = np * 16 + (quad >> 1) * 8 + idx8;
                const int kwrd = kb * 8 + (quad & 1) * 4;
                uint32_t r0, r1, r2, r3;
                ldmatrix_x4(r0, r1, r2, r3, ks_base + (uint32_t)((krow * KP + kwrd) * 4));
                mma_f16(c[2 * np],     qa[kb][0], qa[kb][1], qa[kb][2], qa[kb][3], r0, r1);
                mma_f16(c[2 * np + 1], qa[kb][0], qa[kb][1], qa[kb][2], qa[kb][3], r2, r3);
            }
        }

        // ---- scale + causal mask ----
        const bool diag = (jt * 64 + 63 > wr0);
#pragma unroll
        for (int nf = 0; nf < 8; nf++) {
#pragma unroll
            for (int r = 0; r < 4; r++) {
                float v = c[nf][r] * 0.125f;
                if (diag) {
                    const int col = jt * 64 + nf * 8 + 2 * tq + (r & 1);
                    const int row = wr0 + g + ((r >= 2) ? 8 : 0);
                    if (col > row) v = -1e30f;
                }
                c[nf][r] = v;
            }
        }

        // ---- online softmax (rows g and g+8; reduce over quad lanes) ----
        float tm0 = -1e30f, tm1 = -1e30f;
#pragma unroll
        for (int nf = 0; nf < 8; nf++) {
            tm0 = fmaxf(tm0, fmaxf(c[nf][0], c[nf][1]));
            tm1 = fmaxf(tm1, fmaxf(c[nf][2], c[nf][3]));
        }
#pragma unroll
        for (int off = 1; off <= 2; off <<= 1) {
            tm0 = fmaxf(tm0, __shfl_xor_sync(0xffffffffu, tm0, off));
            tm1 = fmaxf(tm1, __shfl_xor_sync(0xffffffffu, tm1, off));
        }
        const float nm0 = fmaxf(m0, tm0);
        const float nm1 = fmaxf(m1, tm1);
        const float al0 = __expf(m0 - nm0);
        const float al1 = __expf(m1 - nm1);
        float rs0 = 0.0f, rs1 = 0.0f;
#pragma unroll
        for (int nf = 0; nf < 8; nf++) {
            c[nf][0] = __expf(c[nf][0] - nm0);
            c[nf][1] = __expf(c[nf][1] - nm0);
            c[nf][2] = __expf(c[nf][2] - nm1);
            c[nf][3] = __expf(c[nf][3] - nm1);
            rs0 += c[nf][0] + c[nf][1];
            rs1 += c[nf][2] + c[nf][3];
        }
#pragma unroll
        for (int off = 1; off <= 2; off <<= 1) {
            rs0 += __shfl_xor_sync(0xffffffffu, rs0, off);
            rs1 += __shfl_xor_sync(0xffffffffu, rs1, off);
        }
        l0 = l0 * al0 + rs0;  m0 = nm0;
        l1 = l1 * al1 + rs1;  m1 = nm1;
#pragma unroll
        for (int nf = 0; nf < 8; nf++) {
            o[nf][0] *= al0;  o[nf][1] *= al0;
            o[nf][2] *= al1;  o[nf][3] *= al1;
        }

        // ---- O += P @ V  (P packed from S regs; V via ldmatrix.trans) ----
#pragma unroll
        for (int kb2 = 0; kb2 < 4; kb2++) {
            const uint32_t a0 = pack_f16(c[2 * kb2][0],     c[2 * kb2][1]);
            const uint32_t a1 = pack_f16(c[2 * kb2][2],     c[2 * kb2][3]);
            const uint32_t a2 = pack_f16(c[2 * kb2 + 1][0], c[2 * kb2 + 1][1]);
            const uint32_t a3 = pack_f16(c[2 * kb2 + 1][2], c[2 * kb2 + 1][3]);
#pragma unroll
            for (int np = 0; np < 4; np++) {
                const int vrow = kb2 * 16 + (quad & 1) * 8 + idx8;
                const int vwrd = np * 8 + (quad >> 1) * 4;
                uint32_t r0, r1, r2, r3;
                ldmatrix_x4_trans(r0, r1, r2, r3, vs_base + (uint32_t)((vrow * KP + vwrd) * 4));
                mma_f16(o[2 * np],     a0, a1, a2, a3, r0, r1);
                mma_f16(o[2 * np + 1], a0, a1, a2, a3, r2, r3);
            }
        }
    }

    // ---- normalize & store to g_Ctx ----
    const float inv0 = 1.0f / l0;
    const float inv1 = 1.0f / l1;
    float* C0 = g_Ctx + ((size_t)(b * SEQ) + wr0 + g) * D_MODEL + h * HDIM;
    float* C1 = g_Ctx + ((size_t)(b * SEQ) + wr0 + g + 8) * D_MODEL + h * HDIM;
#pragma unroll
    for (int nf = 0; nf < 8; nf++) {
        *(float2*)&C0[nf * 8 + 2 * tq] = make_float2(o[nf][0] * inv0, o[nf][1] * inv0);
        *(float2*)&C1[nf * 8 + 2 * tq] = make_float2(o[nf][2] * inv1, o[nf][3] * inv1);
    }
}

// =================================================================================
// Launch
// =================================================================================
extern "C" void kernel_launch(void* const* d_in, const int* in_sizes, int n_in,
                              void* d_out, int out_size)
{
    const float* x  = (const float*)d_in[0];
    const float* Wq = (const float*)d_in[1];
    const float* Wk = (const float*)d_in[2];
    const float* Wv = (const float*)d_in[3];
    const float* Wo = (const float*)d_in[4];
    float* out = (float*)d_out;

    bf16_gemm<1><<<dim3(D_MODEL / 128, NROWS / 128, 3), 256>>>(x, Wq, Wk, Wv, nullptr);

    attn_mma_kernel<<<dim3(SEQ / QTILE, NHEADS, BATCH), 256>>>();

    bf16_gemm<0><<<dim3(D_MODEL / 128, NROWS / 128, 1), 256>>>(nullptr, Wo, nullptr, nullptr, out);
}

// round 10
// speedup vs baseline: 3.8380x; 1.0932x over previous
#include <cuda_runtime.h>
#include <cuda_bf16.h>
#include <cuda_fp16.h>
#include <cstdint>

#define D_MODEL 1024
#define NHEADS  16
#define HDIM    64
#define BATCH   2
#define SEQ     2048
#define NROWS   (BATCH * SEQ)   // 4096
#define QTILE   128

// ---------------- scratch (static device globals; no allocations) ----------------
__device__ __half g_Qh[BATCH * NHEADS * SEQ * HDIM];   // [B,H,S,Dh] fp16
__device__ __half g_Kh[BATCH * NHEADS * SEQ * HDIM];
__device__ __half g_Vh[BATCH * NHEADS * SEQ * HDIM];
__device__ __nv_bfloat16 g_Ah[NROWS * D_MODEL];        // A hi: x-split, then ctx-split
__device__ __nv_bfloat16 g_Al[NROWS * D_MODEL];        // A lo
__device__ __nv_bfloat16 g_Wh[4 * D_MODEL * D_MODEL];  // W hi [z][k][n]
__device__ __nv_bfloat16 g_Wl[4 * D_MODEL * D_MODEL];  // W lo

// ---------------- ptx helpers (sm_80-class only; NO tcgen05 on this target) ------
__device__ __forceinline__ void cp16(uint32_t smem, const void* gmem) {
    asm volatile("cp.async.cg.shared.global [%0], [%1], 16;" :: "r"(smem), "l"(gmem));
}
#define CP_COMMIT() asm volatile("cp.async.commit_group;" ::: "memory")
template <int N>
__device__ __forceinline__ void cp_wait() {
    asm volatile("cp.async.wait_group %0;" :: "n"(N) : "memory");
}

__device__ __forceinline__ void ldmatrix_x4(uint32_t& r0, uint32_t& r1,
                                            uint32_t& r2, uint32_t& r3, uint32_t addr) {
    asm volatile("ldmatrix.sync.aligned.m8n8.x4.shared.b16 {%0,%1,%2,%3}, [%4];"
                 : "=r"(r0), "=r"(r1), "=r"(r2), "=r"(r3) : "r"(addr));
}
__device__ __forceinline__ void ldmatrix_x4_trans(uint32_t& r0, uint32_t& r1,
                                                  uint32_t& r2, uint32_t& r3, uint32_t addr) {
    asm volatile("ldmatrix.sync.aligned.m8n8.x4.trans.shared.b16 {%0,%1,%2,%3}, [%4];"
                 : "=r"(r0), "=r"(r1), "=r"(r2), "=r"(r3) : "r"(addr));
}
__device__ __forceinline__ void mma_bf16(float* c,
    uint32_t a0, uint32_t a1, uint32_t a2, uint32_t a3, uint32_t b0, uint32_t b1)
{
    asm volatile(
        "mma.sync.aligned.m16n8k16.row.col.f32.bf16.bf16.f32 "
        "{%0,%1,%2,%3}, {%4,%5,%6,%7}, {%8,%9}, {%0,%1,%2,%3};\n"
        : "+f"(c[0]), "+f"(c[1]), "+f"(c[2]), "+f"(c[3])
        : "r"(a0), "r"(a1), "r"(a2), "r"(a3), "r"(b0), "r"(b1));
}
__device__ __forceinline__ void mma_f16(float* c,
    uint32_t a0, uint32_t a1, uint32_t a2, uint32_t a3, uint32_t b0, uint32_t b1)
{
    asm volatile(
        "mma.sync.aligned.m16n8k16.row.col.f32.f16.f16.f32 "
        "{%0,%1,%2,%3}, {%4,%5,%6,%7}, {%8,%9}, {%0,%1,%2,%3};\n"
        : "+f"(c[0]), "+f"(c[1]), "+f"(c[2]), "+f"(c[3])
        : "r"(a0), "r"(a1), "r"(a2), "r"(a3), "r"(b0), "r"(b1));
}
__device__ __forceinline__ uint32_t pack_f16(float x0, float x1) {
    __half2 h = __floats2half2_rn(x0, x1);
    return *(uint32_t*)&h;
}

// =================================================================================
// Pre-pass: element-wise hi/lo bf16 splits (no transpose; layouts preserved).
// =================================================================================
__global__ __launch_bounds__(256) void split_x_kernel(const float* __restrict__ src)
{
    const size_t i = ((size_t)blockIdx.x * 256 + threadIdx.x) * 4;
    float4 v = *(const float4*)(src + i);
    __nv_bfloat16 h[4] = {__float2bfloat16(v.x), __float2bfloat16(v.y),
                          __float2bfloat16(v.z), __float2bfloat16(v.w)};
    __nv_bfloat16 l[4] = {__float2bfloat16(v.x - __bfloat162float(h[0])),
                          __float2bfloat16(v.y - __bfloat162float(h[1])),
                          __float2bfloat16(v.z - __bfloat162float(h[2])),
                          __float2bfloat16(v.w - __bfloat162float(h[3]))};
    *(uint2*)(g_Ah + i) = *(uint2*)h;
    *(uint2*)(g_Al + i) = *(uint2*)l;
}
__global__ __launch_bounds__(256) void split_w_kernel(
    const float* __restrict__ W0, const float* __restrict__ W1,
    const float* __restrict__ W2, const float* __restrict__ W3)
{
    const float* W = (blockIdx.z == 0) ? W0 : (blockIdx.z == 1) ? W1
                   : (blockIdx.z == 2) ? W2 : W3;
    const size_t o = (size_t)blockIdx.z * D_MODEL * D_MODEL;
    const size_t i = ((size_t)blockIdx.x * 256 + threadIdx.x) * 4;
    float4 v = *(const float4*)(W + i);
    __nv_bfloat16 h[4] = {__float2bfloat16(v.x), __float2bfloat16(v.y),
                          __float2bfloat16(v.z), __float2bfloat16(v.w)};
    __nv_bfloat16 l[4] = {__float2bfloat16(v.x - __bfloat162float(h[0])),
                          __float2bfloat16(v.y - __bfloat162float(h[1])),
                          __float2bfloat16(v.z - __bfloat162float(h[2])),
                          __float2bfloat16(v.w - __bfloat162float(h[3]))};
    *(uint2*)(g_Wh + o + i) = *(uint2*)h;
    *(uint2*)(g_Wl + o + i) = *(uint2*)l;
}

// =================================================================================
// bf16-split 3-pass GEMM v2: cp.async double-buffered, BK=32, pre-split operands.
// Block 128x128, 8 warps (2x4), warp tile 64x32. A smem [m][k] pitch 80B
// (ldmatrix.x4, verified pattern); B smem [k][n] pitch 272B (ldmatrix.x4.trans,
// verified via attention-V). QKV=1: out -> fp16 g_Qh/g_Kh/g_Vh; QKV=0: fp32 Cout.
// =================================================================================
#define STG_AH 0
#define STG_AL 10240
#define STG_BH 20480
#define STG_BL 29184
#define STG_SZ 37888
#define G2SMEM (2 * STG_SZ)   // 75776

template <int QKV>
__global__ __launch_bounds__(256) void bf16_gemm2(float* __restrict__ Cout)
{
    extern __shared__ uint8_t smem[];
    const uint32_t sb = (uint32_t)__cvta_generic_to_shared(smem);
    const int t = threadIdx.x, lane = t & 31, wid = t >> 5;
    const int g = lane >> 2, tq = lane & 3, quad = lane >> 3, idx8 = lane & 7;
    const int wm = (wid & 1) * 64, wn = (wid >> 1) * 32;
    const int m0 = blockIdx.y * 128, n0 = blockIdx.x * 128;
    const int z  = QKV ? (int)blockIdx.z : 3;

    const __nv_bfloat16* Wh = g_Wh + (size_t)z * D_MODEL * D_MODEL;
    const __nv_bfloat16* Wl = g_Wl + (size_t)z * D_MODEL * D_MODEL;

    // cp.async mappings (per thread: 2 chunks per buffer, 8 cp.async per stage)
    const int arow0 = t >> 2;             // A chunk: row, k8=(t&3)*8
    const int ak8   = (t & 3) * 8;
    const int brow0 = t >> 4;             // B chunk: k-row, n8=(t&15)*8
    const int bn8   = (t & 15) * 8;

    float acc[4][4][4];
#pragma unroll
    for (int mf = 0; mf < 4; mf++)
#pragma unroll
        for (int nf = 0; nf < 4; nf++)
#pragma unroll
            for (int r = 0; r < 4; r++) acc[mf][nf][r] = 0.0f;

    auto load_stage = [&](int buf, int ks) {
        const uint32_t base = sb + buf * STG_SZ;
#pragma unroll
        for (int half = 0; half < 2; half++) {
            const int row = arow0 + half * 64;
            const uint32_t d = base + row * 80 + (t & 3) * 16;
            const size_t   s = (size_t)(m0 + row) * D_MODEL + ks + ak8;
            cp16(d + STG_AH, g_Ah + s);
            cp16(d + STG_AL, g_Al + s);
        }
#pragma unroll
        for (int half = 0; half < 2; half++) {
            const int row = brow0 + half * 16;
            const uint32_t d = base + row * 272 + (t & 15) * 16;
            const size_t   s = (size_t)(ks + row) * D_MODEL + n0 + bn8;
            cp16(d + STG_BH, Wh + s);
            cp16(d + STG_BL, Wl + s);
        }
        CP_COMMIT();
    };

    load_stage(0, 0);
    load_stage(1, 32);
    int ks = 64;

    constexpr int NIT = D_MODEL / 32;   // 32
    for (int it = 0; it < NIT; ++it) {
        if (it + 1 < NIT) cp_wait<1>(); else cp_wait<0>();
        __syncthreads();

        const uint32_t ab  = sb + (it & 1) * STG_SZ;
        const uint32_t aAh = ab + STG_AH, aAl = ab + STG_AL;
        const uint32_t aBh = ab + STG_BH, aBl = ab + STG_BL;

#pragma unroll
        for (int kb = 0; kb < 2; kb++) {
            uint32_t ah[4][4], al[4][4], bh[4][2], bl[4][2];
#pragma unroll
            for (int mf = 0; mf < 4; mf++) {
                const uint32_t off =
                    (uint32_t)((wm + mf * 16 + (lane & 15)) * 80 +
                               (kb * 8 + (lane >> 4) * 4) * 4);
                ldmatrix_x4(ah[mf][0], ah[mf][1], ah[mf][2], ah[mf][3], aAh + off);
                ldmatrix_x4(al[mf][0], al[mf][1], al[mf][2], al[mf][3], aAl + off);
            }
#pragma unroll
            for (int np = 0; np < 2; np++) {
                const uint32_t boff =
                    (uint32_t)((kb * 16 + (quad & 1) * 8 + idx8) * 272 +
                               (wn / 2 + np * 8 + (quad >> 1) * 4) * 4);
                uint32_t r0, r1, r2, r3;
                ldmatrix_x4_trans(r0, r1, r2, r3, aBh + boff);
                bh[2 * np][0] = r0; bh[2 * np][1] = r1;
                bh[2 * np + 1][0] = r2; bh[2 * np + 1][1] = r3;
                ldmatrix_x4_trans(r0, r1, r2, r3, aBl + boff);
                bl[2 * np][0] = r0; bl[2 * np][1] = r1;
                bl[2 * np + 1][0] = r2; bl[2 * np + 1][1] = r3;
            }
            // 3 passes: hh, lh, hl
#pragma unroll
            for (int mf = 0; mf < 4; mf++)
#pragma unroll
                for (int nf = 0; nf < 4; nf++)
                    mma_bf16(acc[mf][nf], ah[mf][0], ah[mf][1], ah[mf][2], ah[mf][3],
                             bh[nf][0], bh[nf][1]);
#pragma unroll
            for (int mf = 0; mf < 4; mf++)
#pragma unroll
                for (int nf = 0; nf < 4; nf++)
                    mma_bf16(acc[mf][nf], al[mf][0], al[mf][1], al[mf][2], al[mf][3],
                             bh[nf][0], bh[nf][1]);
#pragma unroll
            for (int mf = 0; mf < 4; mf++)
#pragma unroll
                for (int nf = 0; nf < 4; nf++)
                    mma_bf16(acc[mf][nf], ah[mf][0], ah[mf][1], ah[mf][2], ah[mf][3],
                             bl[nf][0], bl[nf][1]);
        }
        __syncthreads();
        if (it + 2 < NIT) {
            load_stage(it & 1, ks);
            ks += 32;
        }
    }

    // epilogue (verified layout): c0=(g,2tq) c1=(g,2tq+1) c2=(g+8,2tq) c3=(g+8,2tq+1)
#pragma unroll
    for (int mf = 0; mf < 4; mf++) {
#pragma unroll
        for (int nf = 0; nf < 4; nf++) {
            const int n = n0 + wn + nf * 8 + 2 * tq;
#pragma unroll
            for (int half = 0; half < 2; half++) {
                const int m = m0 + wm + mf * 16 + g + half * 8;
                const float c0 = acc[mf][nf][half * 2 + 0];
                const float c1 = acc[mf][nf][half * 2 + 1];
                if (QKV) {
                    const int b  = m >> 11;
                    const int s  = m & (SEQ - 1);
                    const int h  = n >> 6;
                    const int dd = n & (HDIM - 1);
                    __half2 hv = __floats2half2_rn(c0, c1);
                    __half* dst = (z == 0) ? g_Qh : (z == 1) ? g_Kh : g_Vh;
                    *(__half2*)&dst[(((size_t)(b * NHEADS + h)) * SEQ + s) * HDIM + dd] = hv;
                } else {
                    *(float2*)&Cout[(size_t)m * D_MODEL + n] = make_float2(c0, c1);
                }
            }
        }
    }
}

// =================================================================================
// fp16 tensor-core causal flash attention (verified Round-7 core); epilogue writes
// ctx directly as hi/lo bf16 into g_Ah/g_Al (feeds the out-proj GEMM).
// =================================================================================
__global__ __launch_bounds__(256) void attn_mma_kernel()
{
    constexpr int KP = 36;
    __shared__ __align__(16) uint32_t Ks[64 * KP];
    __shared__ __align__(16) uint32_t Vs[64 * KP];

    const int t    = threadIdx.x;
    const int lane = t & 31;
    const int wid  = t >> 5;
    const int g    = lane >> 2;
    const int tq   = lane & 3;
    const int quad = lane >> 3;
    const int idx8 = lane & 7;

    const int qt = (int)gridDim.x - 1 - (int)blockIdx.x;
    const int h  = blockIdx.y;
    const int b  = blockIdx.z;
    const int bh = b * NHEADS + h;
    const __half* Qb = g_Qh + (size_t)bh * SEQ * HDIM;
    const __half* Kb = g_Kh + (size_t)bh * SEQ * HDIM;
    const __half* Vb = g_Vh + (size_t)bh * SEQ * HDIM;
    const int q0  = qt * QTILE;
    const int wr0 = q0 + wid * 16;

    uint32_t qa[4][4];
#pragma unroll
    for (int kb = 0; kb < 4; kb++) {
        const int col = kb * 16 + 2 * tq;
        qa[kb][0] = *(const uint32_t*)&Qb[(size_t)(wr0 + g) * HDIM + col];
        qa[kb][1] = *(const uint32_t*)&Qb[(size_t)(wr0 + g + 8) * HDIM + col];
        qa[kb][2] = *(const uint32_t*)&Qb[(size_t)(wr0 + g) * HDIM + col + 8];
        qa[kb][3] = *(const uint32_t*)&Qb[(size_t)(wr0 + g + 8) * HDIM + col + 8];
    }

    float m0 = -1e30f, m1 = -1e30f, l0 = 0.0f, l1 = 0.0f;
    float o[8][4];
#pragma unroll
    for (int nf = 0; nf < 8; nf++)
#pragma unroll
        for (int r = 0; r < 4; r++) o[nf][r] = 0.0f;

    const uint32_t ks_base = (uint32_t)__cvta_generic_to_shared(Ks);
    const uint32_t vs_base = (uint32_t)__cvta_generic_to_shared(Vs);

    const int lr = t >> 2;
    const int lc = (t & 3) * 4;

    const int njt = (q0 + QTILE) / 64;
    for (int jt = 0; jt < njt; jt++) {
        __syncthreads();
        const __half* Kt = Kb + (size_t)jt * 64 * HDIM;
        const __half* Vt = Vb + (size_t)jt * 64 * HDIM;
        *(uint4*)&Ks[lr * KP + lc]      = *(const uint4*)&Kt[lr * HDIM + lc * 2];
        *(uint4*)&Ks[lr * KP + lc + 16] = *(const uint4*)&Kt[lr * HDIM + (lc + 16) * 2];
        *(uint4*)&Vs[lr * KP + lc]      = *(const uint4*)&Vt[lr * HDIM + lc * 2];
        *(uint4*)&Vs[lr * KP + lc + 16] = *(const uint4*)&Vt[lr * HDIM + (lc + 16) * 2];
        __syncthreads();

        if (jt * 64 > wr0 + 15) continue;

        float c[8][4];
#pragma unroll
        for (int nf = 0; nf < 8; nf++)
#pragma unroll
            for (int r = 0; r < 4; r++) c[nf][r] = 0.0f;

#pragma unroll
        for (int kb = 0; kb < 4; kb++) {
#pragma unroll
            for (int np = 0; np < 4; np++) {
                const int krow = np * 16 + (quad >> 1) * 8 + idx8;
                const int kwrd = kb * 8 + (quad & 1) * 4;
                uint32_t r0, r1, r2, r3;
                ldmatrix_x4(r0, r1, r2, r3, ks_base + (uint32_t)((krow * KP + kwrd) * 4));
                mma_f16(c[2 * np],     qa[kb][0], qa[kb][1], qa[kb][2], qa[kb][3], r0, r1);
                mma_f16(c[2 * np + 1], qa[kb][0], qa[kb][1], qa[kb][2], qa[kb][3], r2, r3);
            }
        }

        const bool diag = (jt * 64 + 63 > wr0);
#pragma unroll
        for (int nf = 0; nf < 8; nf++) {
#pragma unroll
            for (int r = 0; r < 4; r++) {
                float v = c[nf][r] * 0.125f;
                if (diag) {
                    const int col = jt * 64 + nf * 8 + 2 * tq + (r & 1);
                    const int row = wr0 + g + ((r >= 2) ? 8 : 0);
                    if (col > row) v = -1e30f;
                }
                c[nf][r] = v;
            }
        }

        float tm0 = -1e30f, tm1 = -1e30f;
#pragma unroll
        for (int nf = 0; nf < 8; nf++) {
            tm0 = fmaxf(tm0, fmaxf(c[nf][0], c[nf][1]));
            tm1 = fmaxf(tm1, fmaxf(c[nf][2], c[nf][3]));
        }
#pragma unroll
        for (int off = 1; off <= 2; off <<= 1) {
            tm0 = fmaxf(tm0, __shfl_xor_sync(0xffffffffu, tm0, off));
            tm1 = fmaxf(tm1, __shfl_xor_sync(0xffffffffu, tm1, off));
        }
        const float nm0 = fmaxf(m0, tm0);
        const float nm1 = fmaxf(m1, tm1);
        const float al0 = __expf(m0 - nm0);
        const float al1 = __expf(m1 - nm1);
        float rs0 = 0.0f, rs1 = 0.0f;
#pragma unroll
        for (int nf = 0; nf < 8; nf++) {
            c[nf][0] = __expf(c[nf][0] - nm0);
            c[nf][1] = __expf(c[nf][1] - nm0);
            c[nf][2] = __expf(c[nf][2] - nm1);
            c[nf][3] = __expf(c[nf][3] - nm1);
            rs0 += c[nf][0] + c[nf][1];
            rs1 += c[nf][2] + c[nf][3];
        }
#pragma unroll
        for (int off = 1; off <= 2; off <<= 1) {
            rs0 += __shfl_xor_sync(0xffffffffu, rs0, off);
            rs1 += __shfl_xor_sync(0xffffffffu, rs1, off);
        }
        l0 = l0 * al0 + rs0;  m0 = nm0;
        l1 = l1 * al1 + rs1;  m1 = nm1;
#pragma unroll
        for (int nf = 0; nf < 8; nf++) {
            o[nf][0] *= al0;  o[nf][1] *= al0;
            o[nf][2] *= al1;  o[nf][3] *= al1;
        }

#pragma unroll
        for (int kb2 = 0; kb2 < 4; kb2++) {
            const uint32_t a0 = pack_f16(c[2 * kb2][0],     c[2 * kb2][1]);
            const uint32_t a1 = pack_f16(c[2 * kb2][2],     c[2 * kb2][3]);
            const uint32_t a2 = pack_f16(c[2 * kb2 + 1][0], c[2 * kb2 + 1][1]);
            const uint32_t a3 = pack_f16(c[2 * kb2 + 1][2], c[2 * kb2 + 1][3]);
#pragma unroll
            for (int np = 0; np < 4; np++) {
                const int vrow = kb2 * 16 + (quad & 1) * 8 + idx8;
                const int vwrd = np * 8 + (quad >> 1) * 4;
                uint32_t r0, r1, r2, r3;
                ldmatrix_x4_trans(r0, r1, r2, r3, vs_base + (uint32_t)((vrow * KP + vwrd) * 4));
                mma_f16(o[2 * np],     a0, a1, a2, a3, r0, r1);
                mma_f16(o[2 * np + 1], a0, a1, a2, a3, r2, r3);
            }
        }
    }

    // ---- normalize & store ctx as hi/lo bf16 ----
    const float inv0 = 1.0f / l0;
    const float inv1 = 1.0f / l1;
    const size_t r0off = ((size_t)(b * SEQ) + wr0 + g) * D_MODEL + h * HDIM;
    const size_t r1off = ((size_t)(b * SEQ) + wr0 + g + 8) * D_MODEL + h * HDIM;
#pragma unroll
    for (int nf = 0; nf < 8; nf++) {
        const int col = nf * 8 + 2 * tq;
        const float v0 = o[nf][0] * inv0, v1 = o[nf][1] * inv0;
        const float v2 = o[nf][2] * inv1, v3 = o[nf][3] * inv1;
        __nv_bfloat16 h0 = __float2bfloat16(v0), h1 = __float2bfloat16(v1);
        __nv_bfloat16 h2 = __float2bfloat16(v2), h3 = __float2bfloat16(v3);
        __nv_bfloat162 hp0; hp0.x = h0; hp0.y = h1;
        __nv_bfloat162 hp1; hp1.x = h2; hp1.y = h3;
        __nv_bfloat162 lp0;
        lp0.x = __float2bfloat16(v0 - __bfloat162float(h0));
        lp0.y = __float2bfloat16(v1 - __bfloat162float(h1));
        __nv_bfloat162 lp1;
        lp1.x = __float2bfloat16(v2 - __bfloat162float(h2));
        lp1.y = __float2bfloat16(v3 - __bfloat162float(h3));
        *(__nv_bfloat162*)&g_Ah[r0off + col] = hp0;
        *(__nv_bfloat162*)&g_Al[r0off + col] = lp0;
        *(__nv_bfloat162*)&g_Ah[r1off + col] = hp1;
        *(__nv_bfloat162*)&g_Al[r1off + col] = lp1;
    }
}

// =================================================================================
// Launch
// =================================================================================
extern "C" void kernel_launch(void* const* d_in, const int* in_sizes, int n_in,
                              void* d_out, int out_size)
{
    const float* x  = (const float*)d_in[0];
    const float* Wq = (const float*)d_in[1];
    const float* Wk = (const float*)d_in[2];
    const float* Wv = (const float*)d_in[3];
    const float* Wo = (const float*)d_in[4];
    float* out = (float*)d_out;

    cudaFuncSetAttribute(bf16_gemm2<1>, cudaFuncAttributeMaxDynamicSharedMemorySize, G2SMEM);
    cudaFuncSetAttribute(bf16_gemm2<0>, cudaFuncAttributeMaxDynamicSharedMemorySize, G2SMEM);

    split_x_kernel<<<NROWS * D_MODEL / 1024, 256>>>(x);
    split_w_kernel<<<dim3(D_MODEL * D_MODEL / 1024, 1, 4), 256>>>(Wq, Wk, Wv, Wo);

    bf16_gemm2<1><<<dim3(D_MODEL / 128, NROWS / 128, 3), 256, G2SMEM>>>(nullptr);

    attn_mma_kernel<<<dim3(SEQ / QTILE, NHEADS, BATCH), 256>>>();

    bf16_gemm2<0><<<dim3(D_MODEL / 128, NROWS / 128, 1), 256, G2SMEM>>>(out);
}